// round 6
// baseline (speedup 1.0000x reference)
#include <cuda_runtime.h>
#include <math.h>

#define B    128
#define P    8732
#define C    21
#define NOBJ 20
#define NB2  ((B*P)/256)   // 4366 exactly (B*P = 1,117,696 = 256*4366)

// ---------------- device scratch (each slot written exactly once per launch) ----
__device__ unsigned char g_conf_t[B*P];
__device__ float         g_mine[B*P];
__device__ float         g_loss_l[B];
__device__ int           g_numpos[B];
__device__ float         g_ce_pos[NB2];
__device__ float         g_neg_sum[B];
__device__ float         g_ce0;          // lse - conf[0] at (b=0,p=0)

__device__ __forceinline__ float sl1(float x) {
    float a = fabsf(x);
    return a < 1.0f ? 0.5f * a * a : a - 0.5f;
}

// =================== kernel 1: matching, conf_t, loc loss =====================
__global__ __launch_bounds__(256) void k_match(const float* __restrict__ loc,
                                               const float* __restrict__ priors,
                                               const float* __restrict__ targets)
{
    __shared__ float              s_bto[P];      // best truth overlap per prior
    __shared__ unsigned char      s_bti[P];      // best truth idx per prior
    __shared__ float              s_tr[NOBJ*5];
    __shared__ unsigned long long s_bp[NOBJ];    // per-truth best prior key
    __shared__ float              s_red[256];
    __shared__ int                s_redi[256];

    int b = blockIdx.x, tid = threadIdx.x;
    if (tid < NOBJ*5) s_tr[tid] = targets[b*NOBJ*5 + tid];
    if (tid < NOBJ)   s_bp[tid] = 0ull;
    __syncthreads();

    unsigned long long bp[NOBJ];
    #pragma unroll
    for (int n = 0; n < NOBJ; n++) bp[n] = 0ull;

    for (int p = tid; p < P; p += 256) {
        float4 pr = ((const float4*)priors)[p];               // cx,cy,w,h
        float bx0 = pr.x - pr.z * 0.5f, by0 = pr.y - pr.w * 0.5f;
        float bx1 = pr.x + pr.z * 0.5f, by1 = pr.y + pr.w * 0.5f;
        float area_b = (bx1 - bx0) * (by1 - by0);
        float best = -1.0f; int bestn = 0;
        #pragma unroll
        for (int n = 0; n < NOBJ; n++) {
            float a0 = s_tr[n*5+0], a1 = s_tr[n*5+1];
            float a2 = s_tr[n*5+2], a3 = s_tr[n*5+3];
            float ltx = fmaxf(a0, bx0), lty = fmaxf(a1, by0);
            float rbx = fminf(a2, bx1), rby = fminf(a3, by1);
            float w = fmaxf(rbx - ltx, 0.0f), h = fmaxf(rby - lty, 0.0f);
            float inter = w * h;
            float area_a = (a2 - a0) * (a3 - a1);
            float iou = inter / (area_a + area_b - inter);
            if (iou > best) { best = iou; bestn = n; }   // strict > = first-occurrence argmax over n
            // key: max val, tie -> smallest p (JAX argmax axis=1 first occurrence)
            unsigned long long key = ((unsigned long long)__float_as_uint(iou) << 32)
                                   | (unsigned long long)(0xFFFFFFFFu - (unsigned)p);
            if (key > bp[n]) bp[n] = key;
        }
        s_bto[p] = best;
        s_bti[p] = (unsigned char)bestn;
    }
    // reduce per-truth best prior: warp shuffle then shared atomics
    #pragma unroll
    for (int n = 0; n < NOBJ; n++) {
        unsigned long long k = bp[n];
        #pragma unroll
        for (int o = 16; o > 0; o >>= 1) {
            unsigned long long other = __shfl_down_sync(0xffffffff, k, o);
            if (other > k) k = other;
        }
        if ((tid & 31) == 0) atomicMax(&s_bp[n], k);
    }
    __syncthreads();
    if (tid == 0) {
        // ascending n: later n overwrites => "chosen = max n" semantics; overlap forced to 2.0
        for (int n = 0; n < NOBJ; n++) {
            unsigned p2 = 0xFFFFFFFFu - (unsigned)(s_bp[n] & 0xFFFFFFFFull);
            s_bto[p2] = 2.0f;
            s_bti[p2] = (unsigned char)n;
        }
    }
    __syncthreads();

    float ll = 0.0f; int np = 0;
    for (int p = tid; p < P; p += 256) {
        int n = s_bti[p];
        int cf = (s_bto[p] < 0.5f) ? 0 : ((int)s_tr[n*5+4] + 1);
        g_conf_t[b*P + p] = (unsigned char)cf;
        if (cf > 0) {
            np++;
            float4 pr = ((const float4*)priors)[p];
            float a0 = s_tr[n*5+0], a1 = s_tr[n*5+1];
            float a2 = s_tr[n*5+2], a3 = s_tr[n*5+3];
            float gx = ((a0 + a2) * 0.5f - pr.x) / (0.1f * pr.z);
            float gy = ((a1 + a3) * 0.5f - pr.y) / (0.1f * pr.w);
            float gw = logf((a2 - a0) / pr.z) / 0.2f;
            float gh = logf((a3 - a1) / pr.w) / 0.2f;
            float4 ld = ((const float4*)loc)[b*P + p];
            ll += sl1(ld.x - gx) + sl1(ld.y - gy) + sl1(ld.z - gw) + sl1(ld.w - gh);
        }
    }
    s_red[tid] = ll; s_redi[tid] = np; __syncthreads();
    for (int o = 128; o > 0; o >>= 1) {
        if (tid < o) { s_red[tid] += s_red[tid + o]; s_redi[tid] += s_redi[tid + o]; }
        __syncthreads();
    }
    if (tid == 0) { g_loss_l[b] = s_red[0]; g_numpos[b] = s_redi[0]; }
}

// =================== kernel 2: logsumexp / CE / mining values ================
__global__ __launch_bounds__(256) void k_lse(const float* __restrict__ conf)
{
    int idx = blockIdx.x * 256 + threadIdx.x;    // grid exactly covers B*P
    const float* row = conf + (size_t)idx * C;
    float v[C];
    #pragma unroll
    for (int c = 0; c < C; c++) v[c] = __ldg(row + c);
    float m = v[0];
    #pragma unroll
    for (int c = 1; c < C; c++) m = fmaxf(m, v[c]);
    float s = 0.0f;
    #pragma unroll
    for (int c = 0; c < C; c++) s += __expf(v[c] - m);
    float lse = m + __logf(s);

    int ct = (int)g_conf_t[idx];
    float cep = 0.0f;
    if (ct > 0) {
        float vc = v[0];
        #pragma unroll
        for (int c = 1; c < C; c++) if (c == ct) vc = v[c];
        cep = lse - vc;
        g_mine[idx] = -1.0f;                     // positives excluded from mining
    } else {
        // clamped[0] = 1 (guaranteed: every row has >=1 positive)
        float vc = (idx == 0) ? v[1] : v[0];
        g_mine[idx] = lse - vc;
    }
    if (idx == 0) g_ce0 = lse - v[0];            // actual CE for (0,0) if negative

    __shared__ float s_red[256];
    s_red[threadIdx.x] = cep; __syncthreads();
    for (int o = 128; o > 0; o >>= 1) {
        if (threadIdx.x < o) s_red[threadIdx.x] += s_red[threadIdx.x + o];
        __syncthreads();
    }
    if (threadIdx.x == 0) g_ce_pos[blockIdx.x] = s_red[0];
}

// =================== kernel 3: hard negative mining (exact top-k) ============
__global__ __launch_bounds__(256) void k_mine()
{
    __shared__ float    s_v[P];
    __shared__ int      hist[256];
    __shared__ int      cnts[256];
    __shared__ unsigned s_pref;
    __shared__ int      s_kleft;
    __shared__ float    s_red[256];

    int b = blockIdx.x, tid = threadIdx.x;
    for (int p = tid; p < P; p += 256) s_v[p] = g_mine[b*P + p];
    __syncthreads();

    int np = g_numpos[b];
    int k = 3 * np; if (k > P - 1) k = P - 1;
    int negc = P - np;
    const int CH = (P + 255) / 256;              // 35
    int lo = tid * CH, hi = min(lo + CH, P);

    float sum = 0.0f;

    if (k >= negc) {
        // select all negatives (extra quota spills onto zero-loss positives -> no-op)
        for (int i = lo; i < hi; i++) { float v = s_v[i]; if (v >= 0.0f) sum += v; }
        if (b == 0 && tid == 0) { float v0 = s_v[0]; if (v0 >= 0.0f) sum += g_ce0 - v0; }
    } else {
        // MSB-first radix select on float bits (all mining values >= 0 -> monotone bits)
        unsigned pref = 0; int kleft = k;
        for (int shift = 24; shift >= 0; shift -= 8) {
            hist[tid] = 0; __syncthreads();
            for (int i = lo; i < hi; i++) {
                float v = s_v[i];
                unsigned key = (v < 0.0f) ? 0u : __float_as_uint(v);
                unsigned keyhi = key >> shift;
                bool ok = (shift == 24) || ((keyhi >> 8) == pref);
                if (ok) atomicAdd(&hist[keyhi & 255u], 1);
            }
            __syncthreads();
            if (tid == 0) {
                int cum = 0, bsel = 0;
                for (int bb = 255; bb >= 0; bb--) {
                    int c = hist[bb];
                    if (cum + c >= kleft) { bsel = bb; break; }
                    cum += c;
                }
                s_pref = (pref << 8) | (unsigned)bsel;
                s_kleft = kleft - cum;
            }
            __syncthreads();
            pref = s_pref; kleft = s_kleft;
            __syncthreads();
        }
        unsigned T = pref; int quota = kleft;    // quota >= 1 always

        int ct = 0;
        for (int i = lo; i < hi; i++) {
            float v = s_v[i];
            unsigned key = (v < 0.0f) ? 0u : __float_as_uint(v);
            if (key > T) sum += v;
            else if (key == T && v >= 0.0f) ct++;
        }
        cnts[tid] = ct; __syncthreads();
        if (tid == 0) {                          // serial exclusive scan (256)
            int acc = 0;
            for (int t = 0; t < 256; t++) { int c = cnts[t]; cnts[t] = acc; acc += c; }
        }
        __syncthreads();
        int off = cnts[tid], r = 0;
        for (int i = lo; i < hi; i++) {          // ties: stable by ascending index
            float v = s_v[i];
            unsigned key = (v < 0.0f) ? 0u : __float_as_uint(v);
            if (key == T && v >= 0.0f) {
                if (off + r < quota) sum += v;
                r++;
            }
        }
        if (b == 0 && tid == 0) {
            float v0 = s_v[0];
            if (v0 >= 0.0f) {
                unsigned key0 = __float_as_uint(v0);
                // if key0==T, index 0 is first tie (rank 0 < quota) -> selected
                if (key0 >= T) sum += g_ce0 - v0;
            }
        }
    }
    s_red[tid] = sum; __syncthreads();
    for (int o = 128; o > 0; o >>= 1) {
        if (tid < o) s_red[tid] += s_red[tid + o];
        __syncthreads();
    }
    if (tid == 0) g_neg_sum[b] = s_red[0];
}

// =================== kernel 4: final reduction =================================
__global__ __launch_bounds__(256) void k_final(float* __restrict__ out)
{
    __shared__ float s1[256], s2[256];
    __shared__ int   si[256];
    int tid = threadIdx.x;
    float ll = 0.0f, lc = 0.0f; int np = 0;
    for (int i = tid; i < B; i += 256) {
        ll += g_loss_l[i];
        lc += g_neg_sum[i];
        np += g_numpos[i];
    }
    for (int i = tid; i < NB2; i += 256) lc += g_ce_pos[i];
    s1[tid] = ll; s2[tid] = lc; si[tid] = np; __syncthreads();
    for (int o = 128; o > 0; o >>= 1) {
        if (tid < o) { s1[tid] += s1[tid+o]; s2[tid] += s2[tid+o]; si[tid] += si[tid+o]; }
        __syncthreads();
    }
    if (tid == 0) {
        float Nf = (float)si[0];
        out[0] = s1[0] / Nf;
        out[1] = s2[0] / Nf;
    }
}

// =================== launch ====================================================
extern "C" void kernel_launch(void* const* d_in, const int* in_sizes, int n_in,
                              void* d_out, int out_size)
{
    const float *loc = nullptr, *conf = nullptr, *priors = nullptr, *targets = nullptr;
    for (int i = 0; i < n_in; i++) {
        long long sz = in_sizes[i];
        if      (sz == (long long)B*P*4)     loc     = (const float*)d_in[i];
        else if (sz == (long long)B*P*C)     conf    = (const float*)d_in[i];
        else if (sz == (long long)P*4)       priors  = (const float*)d_in[i];
        else if (sz == (long long)B*NOBJ*5)  targets = (const float*)d_in[i];
    }
    float* out = (float*)d_out;

    k_match<<<B, 256>>>(loc, priors, targets);
    k_lse  <<<NB2, 256>>>(conf);
    k_mine <<<B, 256>>>();
    k_final<<<1, 256>>>(out);
    (void)out_size;
}

// round 7
// speedup vs baseline: 1.5074x; 1.5074x over previous
#include <cuda_runtime.h>
#include <math.h>

#define B    128
#define P    8732
#define C    21
#define NOBJ 20
#define NT   1024
#define TILE 1024

typedef unsigned long long ull;

// per-image partials
__device__ float g_ll[B];
__device__ float g_lc[B];
__device__ int   g_np[B];

// ---- dynamic shared memory layout (bytes) ----
#define OFF_V      0                         // P floats: overlap (phase1) then mining vals (phase2/3)
#define OFF_STAGE  (OFF_V + P*4)             // TILE*C floats = 86016 B
#define OFF_RED    (OFF_STAGE + TILE*C*4)    // NT floats
#define OFF_REDI   (OFF_RED + NT*4)          // NT ints
#define OFF_HIST   (OFF_REDI + NT*4)         // 256 ints
#define OFF_SUF    (OFF_HIST + 256*4)        // 256 ints
#define OFF_BP     (OFF_SUF + 256*4)         // NOBJ ull (8-aligned: 131184)
#define OFF_TR     (OFF_BP + NOBJ*8)         // NOBJ*5 floats
#define OFF_WS     (OFF_TR + NOBJ*5*4)       // 32 ints (warp scan sums)
#define OFF_SCAL   (OFF_WS + 32*4)           // s_pref(u32), s_kleft(i32), s_ce0(f32), pad
#define OFF_CF     (OFF_SCAL + 16)           // P bytes
#define SMEM_TOTAL (OFF_CF + P + 4)          // ~140624 B

__device__ __forceinline__ float sl1(float x) {
    float a = fabsf(x);
    return a < 1.0f ? 0.5f * a * a : a - 0.5f;
}

__global__ __launch_bounds__(NT, 1) void k_fused(const float* __restrict__ loc,
                                                 const float* __restrict__ conf,
                                                 const float* __restrict__ priors,
                                                 const float* __restrict__ targets)
{
    extern __shared__ unsigned char sraw[];
    float*         s_v     = (float*)(sraw + OFF_V);
    float*         s_stage = (float*)(sraw + OFF_STAGE);
    float*         s_red   = (float*)(sraw + OFF_RED);
    int*           s_redi  = (int*)  (sraw + OFF_REDI);
    int*           hist    = (int*)  (sraw + OFF_HIST);
    int*           suf     = (int*)  (sraw + OFF_SUF);
    ull*           s_bp    = (ull*)  (sraw + OFF_BP);
    float*         s_tr    = (float*)(sraw + OFF_TR);
    int*           s_ws    = (int*)  (sraw + OFF_WS);
    unsigned*      s_pref  = (unsigned*)(sraw + OFF_SCAL);
    int*           s_kleft = (int*)  (sraw + OFF_SCAL + 4);
    float*         s_ce0   = (float*)(sraw + OFF_SCAL + 8);
    unsigned char* s_cf    = (unsigned char*)(sraw + OFF_CF);

    int b = blockIdx.x, tid = threadIdx.x;
    int lane = tid & 31, wid = tid >> 5;

    if (tid < NOBJ*5) s_tr[tid] = targets[b*NOBJ*5 + tid];
    if (tid < NOBJ)   s_bp[tid] = 0ull;
    __syncthreads();

    // ================= phase 1: matching ==========================
    // Each chunk: thread owns one prior (priors read from DRAM once).
    for (int base = 0; base < P; base += NT) {
        int p = base + tid;
        bool act = p < P;
        int pc = act ? p : (P - 1);
        float4 pr = __ldg(((const float4*)priors) + pc);
        float bx0 = pr.x - pr.z * 0.5f, by0 = pr.y - pr.w * 0.5f;
        float bx1 = pr.x + pr.z * 0.5f, by1 = pr.y + pr.w * 0.5f;
        float area_b = (bx1 - bx0) * (by1 - by0);
        float best = -1.0f; int bestn = 0;
        #pragma unroll
        for (int n = 0; n < NOBJ; n++) {
            float a0 = s_tr[n*5+0], a1 = s_tr[n*5+1];
            float a2 = s_tr[n*5+2], a3 = s_tr[n*5+3];
            float w = fmaxf(fminf(a2, bx1) - fmaxf(a0, bx0), 0.0f);
            float h = fmaxf(fminf(a3, by1) - fmaxf(a1, by0), 0.0f);
            float inter = w * h;
            float area_a = (a2 - a0) * (a3 - a1);
            float iou = inter / (area_a + area_b - inter);
            if (iou > best) { best = iou; bestn = n; }    // first-occurrence argmax over n
            // per-truth best prior: max iou, tie -> smallest p
            ull key = act ? ((ull)__float_as_uint(iou) << 32)
                            | (ull)(0xFFFFFFFFu - (unsigned)p)
                          : 0ull;
            #pragma unroll
            for (int o = 16; o > 0; o >>= 1) {
                ull other = __shfl_down_sync(0xffffffffu, key, o);
                if (other > key) key = other;
            }
            if (lane == 0) atomicMax(&s_bp[n], key);
        }
        if (act) { s_v[p] = best; s_cf[p] = (unsigned char)bestn; }
    }
    __syncthreads();
    if (tid == 0) {
        // ascending n: later n overwrites => JAX "chosen = max n"; force overlap 2.0
        for (int n = 0; n < NOBJ; n++) {
            unsigned p2 = 0xFFFFFFFFu - (unsigned)(s_bp[n] & 0xFFFFFFFFull);
            s_v[p2] = 2.0f;
            s_cf[p2] = (unsigned char)n;
        }
    }
    __syncthreads();

    // ============ phase 1b: conf_t, loc loss, numpos ==============
    float ll = 0.0f; int np = 0;
    for (int p = tid; p < P; p += NT) {
        int n = s_cf[p];
        int cf = (s_v[p] < 0.5f) ? 0 : ((int)s_tr[n*5+4] + 1);
        s_cf[p] = (unsigned char)cf;
        if (cf > 0) {
            np++;
            float4 pr = __ldg(((const float4*)priors) + p);
            float a0 = s_tr[n*5+0], a1 = s_tr[n*5+1];
            float a2 = s_tr[n*5+2], a3 = s_tr[n*5+3];
            float gx = ((a0 + a2) * 0.5f - pr.x) / (0.1f * pr.z);
            float gy = ((a1 + a3) * 0.5f - pr.y) / (0.1f * pr.w);
            float gw = logf((a2 - a0) / pr.z) * 5.0f;
            float gh = logf((a3 - a1) / pr.w) * 5.0f;
            float4 ld = __ldg(((const float4*)loc) + (size_t)b*P + p);
            ll += sl1(ld.x - gx) + sl1(ld.y - gy) + sl1(ld.z - gw) + sl1(ld.w - gh);
        }
    }
    s_red[tid] = ll; s_redi[tid] = np; __syncthreads();
    for (int o = NT/2; o > 0; o >>= 1) {
        if (tid < o) { s_red[tid] += s_red[tid + o]; s_redi[tid] += s_redi[tid + o]; }
        __syncthreads();
    }
    float ll_tot = s_red[0];
    int   np_tot = s_redi[0];
    __syncthreads();

    // ============ phase 2: logsumexp / CE / mining values =========
    const float* crow = conf + (size_t)b * P * C;
    float ce_acc = 0.0f;
    for (int tile = 0; tile < P; tile += TILE) {
        int rows = min(TILE, P - tile);
        int elems = rows * C;
        for (int i = tid; i < elems; i += NT)               // fully coalesced DRAM stream
            s_stage[i] = __ldg(crow + (size_t)tile * C + i);
        __syncthreads();
        if (tid < rows) {
            int p = tile + tid;
            const float* r = s_stage + tid * C;              // stride 21 = conflict-free
            float m = r[0];
            #pragma unroll
            for (int c = 1; c < C; c++) m = fmaxf(m, r[c]);
            float s = 0.0f;
            #pragma unroll
            for (int c = 0; c < C; c++) s += __expf(r[c] - m);
            float lse = m + __logf(s);
            int cf = s_cf[p];
            if (cf > 0) {
                ce_acc += lse - r[cf];
                s_v[p] = -1.0f;                              // positives excluded from mining
            } else {
                float vc = (b == 0 && p == 0) ? r[1] : r[0]; // clamped[0]=1 quirk
                s_v[p] = lse - vc;
                if (b == 0 && p == 0) *s_ce0 = lse - r[0];   // true CE for (0,0)
            }
        }
        __syncthreads();
    }

    // ============ phase 3: hard negative mining (exact top-k) =====
    int k = 3 * np_tot; if (k > P - 1) k = P - 1;
    int negc = P - np_tot;
    const int CH = (P + NT - 1) / NT;                        // 9
    int lo = tid * CH, hi = min(lo + CH, P);
    float nsum = 0.0f;

    if (k >= negc) {
        for (int i = lo; i < hi; i++) { float v = s_v[i]; if (v >= 0.0f) nsum += v; }
        if (b == 0 && tid == 0) { float v0 = s_v[0]; if (v0 >= 0.0f) nsum += *s_ce0 - v0; }
    } else {
        unsigned pref = 0; int kleft = k;
        for (int shift = 24; shift >= 0; shift -= 8) {
            if (tid < 256) hist[tid] = 0;
            __syncthreads();
            for (int i = lo; i < hi; i++) {
                float v = s_v[i];
                unsigned key = (v < 0.0f) ? 0u : __float_as_uint(v);
                unsigned kh = key >> shift;
                bool ok = (shift == 24) || ((kh >> 8) == pref);
                if (ok) atomicAdd(&hist[kh & 255u], 1);
            }
            __syncthreads();
            if (tid < 256) suf[tid] = hist[tid];
            __syncthreads();
            #pragma unroll
            for (int off = 1; off < 256; off <<= 1) {        // parallel suffix scan
                int v2 = (tid < 256 - off) ? suf[tid + off] : 0;
                __syncthreads();
                if (tid < 256) suf[tid] += v2;
                __syncthreads();
            }
            if (tid < 256) {
                int here = suf[tid];
                int next = (tid == 255) ? 0 : suf[tid + 1];
                if (here >= kleft && next < kleft) {
                    *s_pref  = (pref << 8) | (unsigned)tid;
                    *s_kleft = kleft - next;
                }
            }
            __syncthreads();
            pref = *s_pref; kleft = *s_kleft;
            __syncthreads();
        }
        unsigned T = pref; int quota = kleft;                // quota >= 1

        int ct = 0;
        for (int i = lo; i < hi; i++) {
            float v = s_v[i];
            unsigned key = (v < 0.0f) ? 0u : __float_as_uint(v);
            if (key > T) nsum += v;
            else if (key == T && v >= 0.0f) ct++;
        }
        // exclusive scan of tie counts across 1024 threads
        int cin = ct;
        #pragma unroll
        for (int o = 1; o < 32; o <<= 1) {
            int n2 = __shfl_up_sync(0xffffffffu, cin, o);
            if (lane >= o) cin += n2;
        }
        if (lane == 31) s_ws[wid] = cin;
        __syncthreads();
        if (wid == 0) {
            int w = s_ws[lane];
            #pragma unroll
            for (int o = 1; o < 32; o <<= 1) {
                int n2 = __shfl_up_sync(0xffffffffu, w, o);
                if (lane >= o) w += n2;
            }
            s_ws[lane] = w;                                  // inclusive per-warp sums
        }
        __syncthreads();
        int off0 = ((wid == 0) ? 0 : s_ws[wid - 1]) + (cin - ct);
        int r2 = 0;
        for (int i = lo; i < hi; i++) {                      // stable tie-break by index
            float v = s_v[i];
            unsigned key = (v < 0.0f) ? 0u : __float_as_uint(v);
            if (key == T && v >= 0.0f) {
                if (off0 + r2 < quota) nsum += v;
                r2++;
            }
        }
        if (b == 0 && tid == 0) {
            float v0 = s_v[0];
            if (v0 >= 0.0f) {
                unsigned k0 = __float_as_uint(v0);
                if (k0 >= T) nsum += *s_ce0 - v0;            // (0,0) if selected: true CE
            }
        }
    }

    // ============ block reduce + write per-image partials =========
    s_red[tid] = ce_acc + nsum; __syncthreads();
    for (int o = NT/2; o > 0; o >>= 1) {
        if (tid < o) s_red[tid] += s_red[tid + o];
        __syncthreads();
    }
    if (tid == 0) { g_ll[b] = ll_tot; g_lc[b] = s_red[0]; g_np[b] = np_tot; }
}

// ============ final: reduce 128 partials ==========================
__global__ void k_final(float* __restrict__ out)
{
    __shared__ float a[B], c2[B];
    __shared__ int   n2[B];
    int tid = threadIdx.x;
    a[tid] = g_ll[tid]; c2[tid] = g_lc[tid]; n2[tid] = g_np[tid];
    __syncthreads();
    for (int o = B/2; o > 0; o >>= 1) {
        if (tid < o) { a[tid] += a[tid+o]; c2[tid] += c2[tid+o]; n2[tid] += n2[tid+o]; }
        __syncthreads();
    }
    if (tid == 0) {
        float Nf = (float)n2[0];
        out[0] = a[0] / Nf;
        out[1] = c2[0] / Nf;
    }
}

extern "C" void kernel_launch(void* const* d_in, const int* in_sizes, int n_in,
                              void* d_out, int out_size)
{
    const float *loc = nullptr, *conf = nullptr, *priors = nullptr, *targets = nullptr;
    for (int i = 0; i < n_in; i++) {
        long long sz = in_sizes[i];
        if      (sz == (long long)B*P*4)     loc     = (const float*)d_in[i];
        else if (sz == (long long)B*P*C)     conf    = (const float*)d_in[i];
        else if (sz == (long long)P*4)       priors  = (const float*)d_in[i];
        else if (sz == (long long)B*NOBJ*5)  targets = (const float*)d_in[i];
    }
    cudaFuncSetAttribute(k_fused, cudaFuncAttributeMaxDynamicSharedMemorySize, SMEM_TOTAL);
    k_fused<<<B, NT, SMEM_TOTAL>>>(loc, conf, priors, targets);
    k_final<<<1, B>>>((float*)d_out);
    (void)out_size;
}

// round 8
// speedup vs baseline: 1.6057x; 1.0652x over previous
#include <cuda_runtime.h>
#include <math.h>

#define B    128
#define P    8732
#define C    21
#define NOBJ 20
#define S4   4
#define QTR  (P/S4)            // 2183 exactly
#define MT   512
#define NTILES ((P + MT - 1)/MT)  // 18

typedef unsigned long long ull;

__device__ ull           g_bp[B*NOBJ];     // per-(image,truth) best prior key
__device__ unsigned char g_code[B*P];      // bestn | pos<<7
__device__ float         g_mine[B*P];      // neg: loss_c ; pos: -(ce+2)
__device__ float         g_ll[B];
__device__ int           g_np[B];
__device__ float         g_lc[B];
__device__ float         g_ce0;
__device__ unsigned      g_ticket;

__device__ __forceinline__ float sl1(float x) {
    float a = fabsf(x);
    return a < 1.0f ? 0.5f * a * a : a - 0.5f;
}

// ---------------- kernel 0: reset accumulators -------------------------------
__global__ void k_init() {
    int i = blockIdx.x * 256 + threadIdx.x;
    if (i < B*NOBJ) g_bp[i] = 0xFFFFFFFFull;   // key(iou=0, p=0)
    if (i < B)      { g_ll[i] = 0.0f; g_np[i] = 0; }
    if (i == 0)     g_ticket = 0u;
}

// ---------------- kernel 1: matching (IoU), 4 blocks per image ---------------
__global__ __launch_bounds__(256) void k_match1(const float4* __restrict__ priors,
                                                const float*  __restrict__ targets)
{
    __shared__ float s_tr[NOBJ*5];
    __shared__ float s_area[NOBJ];
    __shared__ ull   s_bp[NOBJ];

    int blk = blockIdx.x;
    int b = blk >> 2, quarter = blk & 3;
    int tid = threadIdx.x, lane = tid & 31;

    if (tid < NOBJ*5) s_tr[tid] = targets[b*NOBJ*5 + tid];
    if (tid < NOBJ)   s_bp[tid] = 0ull;
    __syncthreads();
    if (tid < NOBJ)
        s_area[tid] = (s_tr[tid*5+2]-s_tr[tid*5+0])*(s_tr[tid*5+3]-s_tr[tid*5+1]);
    __syncthreads();

    ull bp[NOBJ];
    #pragma unroll
    for (int n = 0; n < NOBJ; n++) bp[n] = 0ull;

    int p0 = quarter * QTR;
    for (int i = tid; i < QTR; i += 256) {
        int p = p0 + i;
        float4 pr = __ldg(priors + p);
        float hw = pr.z * 0.5f, hh = pr.w * 0.5f;
        float bx0 = pr.x - hw, by0 = pr.y - hh;
        float bx1 = pr.x + hw, by1 = pr.y + hh;
        float area_b = (bx1 - bx0) * (by1 - by0);
        unsigned pinv = 0xFFFFFFFFu - (unsigned)p;
        float best = -1.0f; int bestn = 0;
        #pragma unroll
        for (int n = 0; n < NOBJ; n++) {
            float a0 = s_tr[n*5+0], a1 = s_tr[n*5+1];
            float a2 = s_tr[n*5+2], a3 = s_tr[n*5+3];
            float w = fmaxf(fminf(a2, bx1) - fmaxf(a0, bx0), 0.0f);
            float h = fmaxf(fminf(a3, by1) - fmaxf(a1, by0), 0.0f);
            float inter = w * h;
            float uni = (s_area[n] + area_b) - inter;
            float iou = inter / uni;                       // div.rn, same as JAX
            if (iou > best) { best = iou; bestn = n; }     // first-occurrence argmax
            ull key = ((ull)__float_as_uint(iou) << 32) | (ull)pinv;
            if (key > bp[n]) bp[n] = key;
        }
        bool pos = !(best < 0.5f);
        g_code[b*P + p] = (unsigned char)(bestn | (pos ? 0x80 : 0));
    }
    // one reduction per truth: warp shuffle -> smem atomic -> global atomic
    #pragma unroll
    for (int n = 0; n < NOBJ; n++) {
        ull k = bp[n];
        #pragma unroll
        for (int o = 16; o > 0; o >>= 1) {
            ull other = __shfl_down_sync(0xffffffffu, k, o);
            if (other > k) k = other;
        }
        if (lane == 0) atomicMax(&s_bp[n], k);
    }
    __syncthreads();
    if (tid < NOBJ) atomicMax(&g_bp[b*NOBJ + tid], s_bp[tid]);
}

// ---------------- kernel 2: LSE + conf_t + mine values + loc loss ------------
__global__ __launch_bounds__(MT, 2) void k_main(const float*  __restrict__ conf,
                                                const float4* __restrict__ priors,
                                                const float*  __restrict__ loc,
                                                const float*  __restrict__ targets)
{
    __shared__ float s_stage[MT*C];   // reused as reduce buffers afterwards
    __shared__ int   s_p2[NOBJ];
    __shared__ float s_tr[NOBJ*5];

    int tile = blockIdx.x, b = blockIdx.y;
    int t0 = tile * MT;
    int rows = min(MT, P - t0);
    int tid = threadIdx.x;

    const float* src = conf + ((size_t)b*P + t0) * C;
    int elems = rows * C;
    for (int i = tid; i < elems; i += MT) s_stage[i] = __ldg(src + i);
    if (tid < NOBJ*5) s_tr[tid] = targets[b*NOBJ*5 + tid];
    if (tid < NOBJ) {
        ull key = g_bp[b*NOBJ + tid];
        s_p2[tid] = (int)(0xFFFFFFFFu - (unsigned)(key & 0xFFFFFFFFull));
    }
    __syncthreads();

    float ll = 0.0f; int np = 0;
    if (tid < rows) {
        int p = t0 + tid;
        unsigned char code = g_code[b*P + p];
        int n = code & 31; bool pos = (code & 0x80) != 0;
        #pragma unroll
        for (int m = 0; m < NOBJ; m++)
            if (s_p2[m] == p) { n = m; pos = true; }       // ascending m: last wins

        const float* r = s_stage + tid * C;                // stride 21: conflict-free
        float mx = r[0];
        #pragma unroll
        for (int c = 1; c < C; c++) mx = fmaxf(mx, r[c]);
        float s = 0.0f;
        #pragma unroll
        for (int c = 0; c < C; c++) s += __expf(r[c] - mx);
        float lse = mx + __logf(s);

        float outv;
        if (pos) {
            int cf = (int)s_tr[n*5+4] + 1;
            float ce = lse - r[cf];
            outv = -(ce + 2.0f);                           // encode positive CE
            np = 1;
            float4 pr = __ldg(priors + p);
            float a0 = s_tr[n*5+0], a1 = s_tr[n*5+1];
            float a2 = s_tr[n*5+2], a3 = s_tr[n*5+3];
            float gx = ((a0 + a2) * 0.5f - pr.x) / (0.1f * pr.z);
            float gy = ((a1 + a3) * 0.5f - pr.y) / (0.1f * pr.w);
            float gw = logf((a2 - a0) / pr.z) * 5.0f;
            float gh = logf((a3 - a1) / pr.w) * 5.0f;
            float4 ld = __ldg(((const float4*)loc) + (size_t)b*P + p);
            ll = sl1(ld.x - gx) + sl1(ld.y - gy) + sl1(ld.z - gw) + sl1(ld.w - gh);
        } else {
            outv = lse - r[0];
            if (b == 0 && p == 0) { g_ce0 = outv; outv = lse - r[1]; } // clamped[0]=1
        }
        g_mine[(size_t)b*P + p] = outv;
    }
    __syncthreads();                       // stage reads done -> reuse as reducer
    float* s_red  = s_stage;
    int*   s_redi = (int*)(s_stage + MT);
    s_red[tid] = ll; s_redi[tid] = np; __syncthreads();
    for (int o = MT/2; o > 0; o >>= 1) {
        if (tid < o) { s_red[tid] += s_red[tid + o]; s_redi[tid] += s_redi[tid + o]; }
        __syncthreads();
    }
    if (tid == 0) {
        if (s_red[0] != 0.0f) atomicAdd(&g_ll[b], s_red[0]);
        if (s_redi[0] != 0)   atomicAdd(&g_np[b], s_redi[0]);
    }
}

// ---------------- kernel 3: hard-negative mining + final ---------------------
__global__ __launch_bounds__(1024) void k_mine(float* __restrict__ out)
{
    __shared__ float    s_v[P];
    __shared__ int      hist[256];
    __shared__ int      cnts[1024 + 32];
    __shared__ float    s_red[1024];
    __shared__ unsigned s_pref;
    __shared__ int      s_kleft;
    __shared__ bool     s_last;

    int b = blockIdx.x, tid = threadIdx.x;
    int lane = tid & 31, wid = tid >> 5;
    int* s_ws = cnts + 1024;

    float ce_pos = 0.0f;
    for (int p = tid; p < P; p += 1024) {
        float v = g_mine[(size_t)b*P + p];
        s_v[p] = v;
        if (v < 0.0f) ce_pos += -v - 2.0f;    // decode positive CE
    }
    __syncthreads();

    int np = g_np[b];
    int k = 3 * np; if (k > P - 1) k = P - 1;
    int negc = P - np;
    const int CH = (P + 1023) / 1024;         // 9
    int lo = tid * CH, hi = min(lo + CH, P);
    float nsum = 0.0f;

    if (k >= negc) {
        for (int i = lo; i < hi; i++) { float v = s_v[i]; if (v >= 0.0f) nsum += v; }
        if (b == 0 && tid == 0) { float v0 = s_v[0]; if (v0 >= 0.0f) nsum += g_ce0 - v0; }
    } else {
        unsigned pref = 0; int kleft = k;
        for (int shift = 24; shift >= 0; shift -= 8) {
            if (tid < 256) hist[tid] = 0;
            __syncthreads();
            for (int i = lo; i < hi; i++) {
                float v = s_v[i];
                unsigned key = (v < 0.0f) ? 0u : __float_as_uint(v);
                unsigned kh = key >> shift;
                bool ok = (shift == 24) || ((kh >> 8) == pref);
                if (ok) atomicAdd(&hist[kh & 255u], 1);
            }
            __syncthreads();
            if (wid == 0) {                   // warp-only bin select (suffix scan)
                int c[8]; int tot = 0;
                #pragma unroll
                for (int j = 0; j < 8; j++) { c[j] = hist[lane*8 + j]; tot += c[j]; }
                int suf = tot;
                #pragma unroll
                for (int o = 1; o < 32; o <<= 1) {
                    int y = __shfl_down_sync(0xffffffffu, suf, o);
                    if (lane + o < 32) suf += y;
                }
                int cum = suf - tot;          // counts strictly above this lane
                #pragma unroll
                for (int j = 7; j >= 0; j--) {
                    if (cum < kleft && cum + c[j] >= kleft) {
                        s_pref  = (pref << 8) | (unsigned)(lane*8 + j);
                        s_kleft = kleft - cum;
                    }
                    cum += c[j];
                }
            }
            __syncthreads();
            pref = s_pref; kleft = s_kleft;
        }
        unsigned T = pref; int quota = kleft;  // quota >= 1

        int ct = 0;
        for (int i = lo; i < hi; i++) {
            float v = s_v[i];
            unsigned key = (v < 0.0f) ? 0u : __float_as_uint(v);
            if (key > T) nsum += v;
            else if (key == T && v >= 0.0f) ct++;
        }
        int cin = ct;
        #pragma unroll
        for (int o = 1; o < 32; o <<= 1) {
            int n2 = __shfl_up_sync(0xffffffffu, cin, o);
            if (lane >= o) cin += n2;
        }
        if (lane == 31) s_ws[wid] = cin;
        __syncthreads();
        if (wid == 0) {
            int w = s_ws[lane];
            #pragma unroll
            for (int o = 1; o < 32; o <<= 1) {
                int n2 = __shfl_up_sync(0xffffffffu, w, o);
                if (lane >= o) w += n2;
            }
            s_ws[lane] = w;
        }
        __syncthreads();
        int off0 = ((wid == 0) ? 0 : s_ws[wid - 1]) + (cin - ct);
        int r2 = 0;
        for (int i = lo; i < hi; i++) {        // ties: stable by ascending index
            float v = s_v[i];
            unsigned key = (v < 0.0f) ? 0u : __float_as_uint(v);
            if (key == T && v >= 0.0f) {
                if (off0 + r2 < quota) nsum += v;
                r2++;
            }
        }
        if (b == 0 && tid == 0) {
            float v0 = s_v[0];
            if (v0 >= 0.0f && __float_as_uint(v0) >= T) nsum += g_ce0 - v0;
        }
    }

    s_red[tid] = ce_pos + nsum; __syncthreads();
    for (int o = 512; o > 0; o >>= 1) {
        if (tid < o) s_red[tid] += s_red[tid + o];
        __syncthreads();
    }
    if (tid == 0) {
        g_lc[b] = s_red[0];
        __threadfence();
        unsigned t = atomicAdd(&g_ticket, 1u);
        s_last = (t == B - 1);
    }
    __syncthreads();

    if (s_last) {                              // last block: deterministic final
        __threadfence();
        float ll = 0.0f, lc = 0.0f; int npt = 0;
        if (tid < B) { ll = g_ll[tid]; lc = g_lc[tid]; npt = g_np[tid]; }
        s_red[tid] = ll; s_v[tid] = lc; cnts[tid] = npt;
        __syncthreads();
        for (int o = 64; o > 0; o >>= 1) {
            if (tid < o) { s_red[tid] += s_red[tid+o]; s_v[tid] += s_v[tid+o]; cnts[tid] += cnts[tid+o]; }
            __syncthreads();
        }
        if (tid == 0) {
            float Nf = (float)cnts[0];
            out[0] = s_red[0] / Nf;
            out[1] = s_v[0] / Nf;
        }
    }
}

// ---------------- launch -------------------------------------------------------
extern "C" void kernel_launch(void* const* d_in, const int* in_sizes, int n_in,
                              void* d_out, int out_size)
{
    const float *loc = nullptr, *conf = nullptr, *priors = nullptr, *targets = nullptr;
    for (int i = 0; i < n_in; i++) {
        long long sz = in_sizes[i];
        if      (sz == (long long)B*P*4)     loc     = (const float*)d_in[i];
        else if (sz == (long long)B*P*C)     conf    = (const float*)d_in[i];
        else if (sz == (long long)P*4)       priors  = (const float*)d_in[i];
        else if (sz == (long long)B*NOBJ*5)  targets = (const float*)d_in[i];
    }
    k_init  <<<(B*NOBJ + 255)/256, 256>>>();
    k_match1<<<B*S4, 256>>>((const float4*)priors, targets);
    dim3 g2(NTILES, B);
    k_main  <<<g2, MT>>>(conf, (const float4*)priors, loc, targets);
    k_mine  <<<B, 1024>>>((float*)d_out);
    (void)out_size;
}